// round 6
// baseline (speedup 1.0000x reference)
#include <cuda_runtime.h>
#include <math.h>

// Problem constants
#define S    2048
#define Hdim 4096
#define NH   32
#define HD   128
#define QKV3 12288            // 3*Hdim
#define HSTRIDE 384           // 3*HD per head inside a qkv row

// Scratch (device globals; no runtime allocation)
__device__ float g_qkv[(size_t)S * QKV3];            // 100 MB
__device__ float g_ctx[(size_t)S * Hdim];            // 33 MB

// ---------------------------------------------------------------------------
// tf32 helpers
// ---------------------------------------------------------------------------
__device__ __forceinline__ float to_tf32(float x) {
    unsigned r;
    asm("cvt.rna.tf32.f32 %0, %1;" : "=r"(r) : "f"(x));
    return __uint_as_float(r);
}

__device__ __forceinline__ void mma8(float c[4], const float4& a, const float2& b) {
    asm volatile(
        "mma.sync.aligned.m16n8k8.row.col.f32.tf32.tf32.f32 "
        "{%0,%1,%2,%3},{%4,%5,%6,%7},{%8,%9},{%0,%1,%2,%3};\n"
        : "+f"(c[0]), "+f"(c[1]), "+f"(c[2]), "+f"(c[3])
        : "r"(__float_as_uint(a.x)), "r"(__float_as_uint(a.y)),
          "r"(__float_as_uint(a.z)), "r"(__float_as_uint(a.w)),
          "r"(__float_as_uint(b.x)), "r"(__float_as_uint(b.y)));
}

// Shared-tile layouts:
//  A-frag layout: As4[kb][p][c] : float4 = (A[m1][k], A[m1+8][k], A[m1][k+4], A[m1+8][k+4])
//                 k = kb*8+c, m1 = ((p>>3)<<4)+(p&7), rows m1 / m1+8
//  B-frag layout: Bs2[kb][n][c] : float2 = (B[n][k], B[n][k+4]), k = kb*8+c

// ---------------------------------------------------------------------------
// Generic NT GEMM: C[m,n] = sum_k A[m,k]*B[n,k] + bias[n]  (unchanged)
// ---------------------------------------------------------------------------
__global__ __launch_bounds__(256) void gemm_tc_nt(
    const float* __restrict__ A, const float* __restrict__ B,
    const float* __restrict__ bias, float* __restrict__ C,
    int K, int lda, int ldb, int ldc)
{
    __shared__ float4 As4[4][64][4];   // 16 KB
    __shared__ float2 Bs2[4][128][4];  // 16 KB

    const int tid = threadIdx.x, lane = tid & 31, wid = tid >> 5;
    const int warp_m = wid & 1, warp_n = wid >> 1;
    const int t4 = lane >> 2, c4 = lane & 3;

    const int kbA = tid & 3, pA = tid >> 2;
    const int m1  = ((pA >> 3) << 4) + (pA & 7);
    const int kbB = tid & 3, nB = tid >> 2;

    const float* a1p = A + (size_t)(blockIdx.y * 128 + m1) * lda + kbA * 8;
    const float* a2p = a1p + (size_t)8 * lda;
    const float* b1p = B + (size_t)(blockIdx.x * 128 + nB) * ldb + kbB * 8;
    const float* b2p = b1p + (size_t)64 * ldb;

    float acc[4][4][4];
#pragma unroll
    for (int i = 0; i < 4; i++)
#pragma unroll
        for (int j = 0; j < 4; j++)
#pragma unroll
            for (int r = 0; r < 4; r++) acc[i][j][r] = 0.f;

    float4 xa0, xa1, ya0, ya1, u0, u1, v0, v1;
    xa0 = *(const float4*)(a1p);     xa1 = *(const float4*)(a1p + 4);
    ya0 = *(const float4*)(a2p);     ya1 = *(const float4*)(a2p + 4);
    u0  = *(const float4*)(b1p);     u1  = *(const float4*)(b1p + 4);
    v0  = *(const float4*)(b2p);     v1  = *(const float4*)(b2p + 4);

    for (int k0 = 0; k0 < K; k0 += 32) {
        __syncthreads();
        As4[kbA][pA][0] = make_float4(to_tf32(xa0.x), to_tf32(ya0.x), to_tf32(xa1.x), to_tf32(ya1.x));
        As4[kbA][pA][1] = make_float4(to_tf32(xa0.y), to_tf32(ya0.y), to_tf32(xa1.y), to_tf32(ya1.y));
        As4[kbA][pA][2] = make_float4(to_tf32(xa0.z), to_tf32(ya0.z), to_tf32(xa1.z), to_tf32(ya1.z));
        As4[kbA][pA][3] = make_float4(to_tf32(xa0.w), to_tf32(ya0.w), to_tf32(xa1.w), to_tf32(ya1.w));
        Bs2[kbB][nB][0]      = make_float2(to_tf32(u0.x), to_tf32(u1.x));
        Bs2[kbB][nB][1]      = make_float2(to_tf32(u0.y), to_tf32(u1.y));
        Bs2[kbB][nB][2]      = make_float2(to_tf32(u0.z), to_tf32(u1.z));
        Bs2[kbB][nB][3]      = make_float2(to_tf32(u0.w), to_tf32(u1.w));
        Bs2[kbB][nB + 64][0] = make_float2(to_tf32(v0.x), to_tf32(v1.x));
        Bs2[kbB][nB + 64][1] = make_float2(to_tf32(v0.y), to_tf32(v1.y));
        Bs2[kbB][nB + 64][2] = make_float2(to_tf32(v0.z), to_tf32(v1.z));
        Bs2[kbB][nB + 64][3] = make_float2(to_tf32(v0.w), to_tf32(v1.w));
        __syncthreads();

        int kn = k0 + 32;
        if (kn < K) {
            xa0 = *(const float4*)(a1p + kn);     xa1 = *(const float4*)(a1p + kn + 4);
            ya0 = *(const float4*)(a2p + kn);     ya1 = *(const float4*)(a2p + kn + 4);
            u0  = *(const float4*)(b1p + kn);     u1  = *(const float4*)(b1p + kn + 4);
            v0  = *(const float4*)(b2p + kn);     v1  = *(const float4*)(b2p + kn + 4);
        }

#pragma unroll
        for (int kb = 0; kb < 4; kb++) {
            float4 af[4]; float2 bf[4];
#pragma unroll
            for (int mt = 0; mt < 4; mt++)
                af[mt] = As4[kb][((warp_m * 4 + mt) << 3) + t4][c4];
#pragma unroll
            for (int nt = 0; nt < 4; nt++)
                bf[nt] = Bs2[kb][warp_n * 32 + nt * 8 + t4][c4];
#pragma unroll
            for (int mt = 0; mt < 4; mt++)
#pragma unroll
                for (int nt = 0; nt < 4; nt++) mma8(acc[mt][nt], af[mt], bf[nt]);
        }
    }

#pragma unroll
    for (int mt = 0; mt < 4; mt++) {
        int r0 = blockIdx.y * 128 + warp_m * 64 + mt * 16 + t4;
#pragma unroll
        for (int nt = 0; nt < 4; nt++) {
            int cc = blockIdx.x * 128 + warp_n * 32 + nt * 8 + 2 * c4;
            float b0 = bias[cc], b1 = bias[cc + 1];
            *(float2*)&C[(size_t)r0 * ldc + cc] =
                make_float2(acc[mt][nt][0] + b0, acc[mt][nt][1] + b1);
            *(float2*)&C[(size_t)(r0 + 8) * ldc + cc] =
                make_float2(acc[mt][nt][2] + b0, acc[mt][nt][3] + b1);
        }
    }
}

// ---------------------------------------------------------------------------
// RoPE (in place on q,k slices of g_qkv)
// ---------------------------------------------------------------------------
__global__ void rope_kernel(float* __restrict__ qkv)
{
    int idx = blockIdx.x * blockDim.x + threadIdx.x;
    const int total = S * NH * 16 * 2;
    if (idx >= total) return;

    int i = idx & 15;
    int r = idx >> 4;
    int h = r & 31;
    r >>= 5;
    int which = r & 1;
    int s = r >> 1;

    float inv = powf(10000.0f, -(float)i / 16.0f);
    float ang = (float)s * inv;
    float c, sn;
    sincosf(ang, &sn, &c);

    float* base = qkv + (size_t)s * QKV3 + h * HSTRIDE + which * HD;
    float x1 = base[i];
    float x2 = base[i + 16];
    base[i]      = x1 * c - x2 * sn;
    base[i + 16] = x2 * c + x1 * sn;
}

// ---------------------------------------------------------------------------
// Flash attention v2: warp-decoupled.
// Block = (head, 128 Q rows); warp w owns rows 16w..16w+15 x ALL 128 keys.
// Warp-local softmax, per-warp P smem, 4 __syncthreads per K-tile.
// Dynamic smem 192KB: Qs 64KB | KVs 64KB (K then V) | Pp 64KB.
// ---------------------------------------------------------------------------
__global__ __launch_bounds__(256) void flash2(
    const float* __restrict__ qkv, float* __restrict__ ctx)
{
    extern __shared__ char smbase[];
    float4 (*Qs)[64][4]   = (float4 (*)[64][4])(smbase);             // [16][64][4]
    float2 (*KVs)[128][4] = (float2 (*)[128][4])(smbase + 65536);    // [16][128][4]
    float4 (*Pp)[16][8][4]= (float4 (*)[16][8][4])(smbase + 131072); // [8][16][8][4]

    const int bi = (int)(gridDim.x - 1 - blockIdx.x);   // heavy tiles first
    const int h  = blockIdx.y;

    const int tid = threadIdx.x, lane = tid & 31, w = tid >> 5;
    const int t4 = lane >> 2, c4 = lane & 3;

    // loader indices
    const int kbA = tid & 3, pA = tid >> 2;                    // A-style loads
    const int m1  = ((pA >> 3) << 4) + (pA & 7);
    const int nB  = tid >> 2;                                  // B-style (keys)
    const int dV  = tid & 127, kbV0 = (tid >> 7) * 2;          // V transpose

    // ---- stage Q once (A-frag layout, tf32) ----
    {
        const float* a1p = qkv + (size_t)(bi * 128 + m1) * QKV3 + h * HSTRIDE;
        const float* a2p = a1p + (size_t)8 * QKV3;
#pragma unroll
        for (int cc = 0; cc < 4; cc++) {
            const float* p1 = a1p + cc * 32 + kbA * 8;
            const float* p2 = a2p + cc * 32 + kbA * 8;
            float4 x0 = *(const float4*)p1, x1 = *(const float4*)(p1 + 4);
            float4 y0 = *(const float4*)p2, y1 = *(const float4*)(p2 + 4);
            int kb = cc * 4 + kbA;
            Qs[kb][pA][0] = make_float4(to_tf32(x0.x), to_tf32(y0.x), to_tf32(x1.x), to_tf32(y1.x));
            Qs[kb][pA][1] = make_float4(to_tf32(x0.y), to_tf32(y0.y), to_tf32(x1.y), to_tf32(y1.y));
            Qs[kb][pA][2] = make_float4(to_tf32(x0.z), to_tf32(y0.z), to_tf32(x1.z), to_tf32(y1.z));
            Qs[kb][pA][3] = make_float4(to_tf32(x0.w), to_tf32(y0.w), to_tf32(x1.w), to_tf32(y1.w));
        }
    }

    float o[16][4];
    float m_run[2] = { -1e30f, -1e30f };
    float l_run[2] = { 0.f, 0.f };
#pragma unroll
    for (int nt = 0; nt < 16; nt++)
#pragma unroll
        for (int r = 0; r < 4; r++) o[nt][r] = 0.f;

    const float scale = 0.08838834764831845f;   // 1/sqrt(128)
    const int c_base = (c4 & 1) * 2;
    const int c_hi   = (c4 >> 1) * 2;

    for (int bj = 0; bj <= bi; bj++) {
        // ---- stage K (full 128 keys x 128 dims, B-frag layout) ----
        {
            const float* b1p = qkv + (size_t)(bj * 128 + nB) * QKV3 + h * HSTRIDE + HD;
            const float* b2p = b1p + (size_t)64 * QKV3;
#pragma unroll
            for (int cc = 0; cc < 4; cc++) {
                const float* p1 = b1p + cc * 32 + kbA * 8;
                const float* p2 = b2p + cc * 32 + kbA * 8;
                float4 u0 = *(const float4*)p1, u1 = *(const float4*)(p1 + 4);
                float4 v0 = *(const float4*)p2, v1 = *(const float4*)(p2 + 4);
                int kb = cc * 4 + kbA;
                KVs[kb][nB][0]      = make_float2(to_tf32(u0.x), to_tf32(u1.x));
                KVs[kb][nB][1]      = make_float2(to_tf32(u0.y), to_tf32(u1.y));
                KVs[kb][nB][2]      = make_float2(to_tf32(u0.z), to_tf32(u1.z));
                KVs[kb][nB][3]      = make_float2(to_tf32(u0.w), to_tf32(u1.w));
                KVs[kb][nB + 64][0] = make_float2(to_tf32(v0.x), to_tf32(v1.x));
                KVs[kb][nB + 64][1] = make_float2(to_tf32(v0.y), to_tf32(v1.y));
                KVs[kb][nB + 64][2] = make_float2(to_tf32(v0.z), to_tf32(v1.z));
                KVs[kb][nB + 64][3] = make_float2(to_tf32(v0.w), to_tf32(v1.w));
            }
        }
        __syncthreads();   // (1) Q (first iter) + K staged

        // ---- Q @ K^T : warp computes 16 rows x 128 keys ----
        float sc[16][4];
#pragma unroll
        for (int nt = 0; nt < 16; nt++)
#pragma unroll
            for (int r = 0; r < 4; r++) sc[nt][r] = 0.f;

#pragma unroll
        for (int kb = 0; kb < 16; kb++) {
            float4 af = Qs[kb][w * 8 + t4][c4];
#pragma unroll
            for (int nt = 0; nt < 16; nt++) {
                float2 bf = KVs[kb][nt * 8 + t4][c4];
                mma8(sc[nt], af, bf);
            }
        }
        __syncthreads();   // (2) all QK reads done; KVs free for V

        // ---- stage V (transposed: B[n=dim][k=key]) — overlaps softmax ----
        {
            const float* vcol = qkv + (size_t)(bj * 128) * QKV3 + h * HSTRIDE + 2 * HD + dV;
#pragma unroll
            for (int g = 0; g < 4; g++) {
                float vv[2][8];
#pragma unroll
                for (int j = 0; j < 2; j++)
#pragma unroll
                    for (int c = 0; c < 8; c++)
                        vv[j][c] = vcol[(size_t)(g * 32 + (kbV0 + j) * 8 + c) * QKV3];
#pragma unroll
                for (int j = 0; j < 2; j++) {
                    int kb = g * 4 + kbV0 + j;
                    KVs[kb][dV][0] = make_float2(to_tf32(vv[j][0]), to_tf32(vv[j][4]));
                    KVs[kb][dV][1] = make_float2(to_tf32(vv[j][1]), to_tf32(vv[j][5]));
                    KVs[kb][dV][2] = make_float2(to_tf32(vv[j][2]), to_tf32(vv[j][6]));
                    KVs[kb][dV][3] = make_float2(to_tf32(vv[j][3]), to_tf32(vv[j][7]));
                }
            }
        }

        // ---- scale + causal mask (local coords: row = 16w+t4(+8), col = 8nt+2c4(+1)) ----
        if (bj == bi) {
            int r0 = w * 16 + t4;
#pragma unroll
            for (int nt = 0; nt < 16; nt++) {
                int cc = nt * 8 + 2 * c4;
                sc[nt][0] = (cc     <= r0    ) ? sc[nt][0] * scale : -1e30f;
                sc[nt][1] = (cc + 1 <= r0    ) ? sc[nt][1] * scale : -1e30f;
                sc[nt][2] = (cc     <= r0 + 8) ? sc[nt][2] * scale : -1e30f;
                sc[nt][3] = (cc + 1 <= r0 + 8) ? sc[nt][3] * scale : -1e30f;
            }
        } else {
#pragma unroll
            for (int nt = 0; nt < 16; nt++)
#pragma unroll
                for (int r = 0; r < 4; r++) sc[nt][r] *= scale;
        }

        // ---- warp-local online softmax (quad shfl only) ----
        float p0 = -1e30f, p1 = -1e30f;
#pragma unroll
        for (int nt = 0; nt < 16; nt++) {
            p0 = fmaxf(p0, fmaxf(sc[nt][0], sc[nt][1]));
            p1 = fmaxf(p1, fmaxf(sc[nt][2], sc[nt][3]));
        }
#pragma unroll
        for (int off = 1; off <= 2; off <<= 1) {
            p0 = fmaxf(p0, __shfl_xor_sync(0xffffffffu, p0, off));
            p1 = fmaxf(p1, __shfl_xor_sync(0xffffffffu, p1, off));
        }
        float mn0 = fmaxf(m_run[0], p0);
        float mn1 = fmaxf(m_run[1], p1);
        float a0 = __expf(m_run[0] - mn0);
        float a1 = __expf(m_run[1] - mn1);
        m_run[0] = mn0;  m_run[1] = mn1;

        float s0 = 0.f, s1 = 0.f;
#pragma unroll
        for (int nt = 0; nt < 16; nt++) {
            sc[nt][0] = __expf(sc[nt][0] - mn0);
            sc[nt][1] = __expf(sc[nt][1] - mn0);
            sc[nt][2] = __expf(sc[nt][2] - mn1);
            sc[nt][3] = __expf(sc[nt][3] - mn1);
            s0 += sc[nt][0] + sc[nt][1];
            s1 += sc[nt][2] + sc[nt][3];
        }
#pragma unroll
        for (int off = 1; off <= 2; off <<= 1) {
            s0 += __shfl_xor_sync(0xffffffffu, s0, off);
            s1 += __shfl_xor_sync(0xffffffffu, s1, off);
        }
        l_run[0] = l_run[0] * a0 + s0;
        l_run[1] = l_run[1] * a1 + s1;

        // rescale O
#pragma unroll
        for (int nt = 0; nt < 16; nt++) {
            o[nt][0] *= a0;  o[nt][1] *= a0;
            o[nt][2] *= a1;  o[nt][3] *= a1;
        }

        // ---- write P to per-warp smem (A-frag layout, tf32) ----
#pragma unroll
        for (int nt = 0; nt < 16; nt++) {
            float* s0p = ((float*)&Pp[w][nt][t4][c_base]) + c_hi;
            s0p[0] = to_tf32(sc[nt][0]);
            s0p[1] = to_tf32(sc[nt][2]);
            float* s1p = ((float*)&Pp[w][nt][t4][c_base + 1]) + c_hi;
            s1p[0] = to_tf32(sc[nt][1]);
            s1p[1] = to_tf32(sc[nt][3]);
        }
        __syncwarp();
        __syncthreads();   // (3) V staged by everyone

        // ---- P @ V ----
#pragma unroll
        for (int kb = 0; kb < 16; kb++) {
            float4 af = Pp[w][kb][t4][c4];
#pragma unroll
            for (int nt = 0; nt < 16; nt++) {
                float2 bf = KVs[kb][nt * 8 + t4][c4];
                mma8(o[nt], af, bf);
            }
        }
        __syncthreads();   // (4) V reads done before next K overwrite
    }

    // ---- epilogue: normalize + store ----
    float inv0 = 1.0f / l_run[0];
    float inv1 = 1.0f / l_run[1];
    int row = bi * 128 + w * 16 + t4;
#pragma unroll
    for (int nt = 0; nt < 16; nt++) {
        int col = h * HD + nt * 8 + 2 * c4;
        *(float2*)&ctx[(size_t)row * Hdim + col] =
            make_float2(o[nt][0] * inv0, o[nt][1] * inv0);
        *(float2*)&ctx[(size_t)(row + 8) * Hdim + col] =
            make_float2(o[nt][2] * inv1, o[nt][3] * inv1);
    }
}

// ---------------------------------------------------------------------------
// Launch
// ---------------------------------------------------------------------------
extern "C" void kernel_launch(void* const* d_in, const int* in_sizes, int n_in,
                              void* d_out, int out_size)
{
    const float* hidden  = (const float*)d_in[0];
    // d_in[1] = attention_mask (causal; structure known, unused)
    const float* W_qkv   = (const float*)d_in[2];
    const float* b_qkv   = (const float*)d_in[3];
    const float* W_dense = (const float*)d_in[4];
    const float* b_dense = (const float*)d_in[5];
    float* out = (float*)d_out;

    float *qkv, *ctx;
    cudaGetSymbolAddress((void**)&qkv, g_qkv);
    cudaGetSymbolAddress((void**)&ctx, g_ctx);

    // 1) QKV GEMM: [2048,4096] x [12288,4096]^T -> [2048,12288]
    {
        dim3 grid(QKV3 / 128, S / 128);
        gemm_tc_nt<<<grid, 256>>>(hidden, W_qkv, b_qkv, qkv,
                                  Hdim, Hdim, Hdim, QKV3);
    }

    // 2) RoPE in place on q,k
    {
        int total = S * NH * 16 * 2;
        rope_kernel<<<(total + 255) / 256, 256>>>(qkv);
    }

    // 3-5) Fused flash attention v2 -> ctx [2048, 4096]
    {
        const int smem_bytes = 192 * 1024;
        cudaFuncSetAttribute(flash2, cudaFuncAttributeMaxDynamicSharedMemorySize,
                             smem_bytes);
        dim3 grid(S / 128, NH);
        flash2<<<grid, 256, smem_bytes>>>(qkv, ctx);
    }

    // 6) Dense GEMM: ctx [2048,4096] x W_dense^T -> out
    {
        dim3 grid(Hdim / 128, S / 128);
        gemm_tc_nt<<<grid, 256>>>(ctx, W_dense, b_dense, out,
                                  Hdim, Hdim, Hdim, Hdim);
    }
}

// round 9
// speedup vs baseline: 1.0738x; 1.0738x over previous
#include <cuda_runtime.h>
#include <math.h>

// Problem constants
#define S    2048
#define Hdim 4096
#define NH   32
#define HD   128
#define QKV3 12288            // 3*Hdim
#define HSTRIDE 384           // 3*HD per head inside a qkv row

// Scratch (device globals; no runtime allocation)
__device__ float g_qkv[(size_t)S * QKV3];            // 100 MB
__device__ float g_ctx[(size_t)S * Hdim];            // 33 MB

// ---------------------------------------------------------------------------
// tf32 helpers
// ---------------------------------------------------------------------------
__device__ __forceinline__ float to_tf32(float x) {
    unsigned r;
    asm("cvt.rna.tf32.f32 %0, %1;" : "=r"(r) : "f"(x));
    return __uint_as_float(r);
}

__device__ __forceinline__ void mma8(float c[4], const float4& a, const float2& b) {
    asm volatile(
        "mma.sync.aligned.m16n8k8.row.col.f32.tf32.tf32.f32 "
        "{%0,%1,%2,%3},{%4,%5,%6,%7},{%8,%9},{%0,%1,%2,%3};\n"
        : "+f"(c[0]), "+f"(c[1]), "+f"(c[2]), "+f"(c[3])
        : "r"(__float_as_uint(a.x)), "r"(__float_as_uint(a.y)),
          "r"(__float_as_uint(a.z)), "r"(__float_as_uint(a.w)),
          "r"(__float_as_uint(b.x)), "r"(__float_as_uint(b.y)));
}

// Shared-tile layouts:
//  A-frag: As4[kb][p][c] : float4 = (A[m1][k], A[m1+8][k], A[m1][k+4], A[m1+8][k+4])
//          k = kb*8+c, m1 = ((p>>3)<<4)+(p&7)
//  B-frag: Bs2[kb][n][c] : float2 = (B[n][k], B[n][k+4]), k = kb*8+c

// ---------------------------------------------------------------------------
// Generic NT GEMM: C[m,n] = sum_k A[m,k]*B[n,k] + bias[n]  (proven, unchanged)
// ---------------------------------------------------------------------------
__global__ __launch_bounds__(256) void gemm_tc_nt(
    const float* __restrict__ A, const float* __restrict__ B,
    const float* __restrict__ bias, float* __restrict__ C,
    int K, int lda, int ldb, int ldc)
{
    __shared__ float4 As4[4][64][4];   // 16 KB
    __shared__ float2 Bs2[4][128][4];  // 16 KB

    const int tid = threadIdx.x, lane = tid & 31, wid = tid >> 5;
    const int warp_m = wid & 1, warp_n = wid >> 1;
    const int t4 = lane >> 2, c4 = lane & 3;

    const int kbA = tid & 3, pA = tid >> 2;
    const int m1  = ((pA >> 3) << 4) + (pA & 7);
    const int kbB = tid & 3, nB = tid >> 2;

    const float* a1p = A + (size_t)(blockIdx.y * 128 + m1) * lda + kbA * 8;
    const float* a2p = a1p + (size_t)8 * lda;
    const float* b1p = B + (size_t)(blockIdx.x * 128 + nB) * ldb + kbB * 8;
    const float* b2p = b1p + (size_t)64 * ldb;

    float acc[4][4][4];
#pragma unroll
    for (int i = 0; i < 4; i++)
#pragma unroll
        for (int j = 0; j < 4; j++)
#pragma unroll
            for (int r = 0; r < 4; r++) acc[i][j][r] = 0.f;

    float4 xa0, xa1, ya0, ya1, u0, u1, v0, v1;
    xa0 = *(const float4*)(a1p);     xa1 = *(const float4*)(a1p + 4);
    ya0 = *(const float4*)(a2p);     ya1 = *(const float4*)(a2p + 4);
    u0  = *(const float4*)(b1p);     u1  = *(const float4*)(b1p + 4);
    v0  = *(const float4*)(b2p);     v1  = *(const float4*)(b2p + 4);

    for (int k0 = 0; k0 < K; k0 += 32) {
        __syncthreads();
        As4[kbA][pA][0] = make_float4(to_tf32(xa0.x), to_tf32(ya0.x), to_tf32(xa1.x), to_tf32(ya1.x));
        As4[kbA][pA][1] = make_float4(to_tf32(xa0.y), to_tf32(ya0.y), to_tf32(xa1.y), to_tf32(ya1.y));
        As4[kbA][pA][2] = make_float4(to_tf32(xa0.z), to_tf32(ya0.z), to_tf32(xa1.z), to_tf32(ya1.z));
        As4[kbA][pA][3] = make_float4(to_tf32(xa0.w), to_tf32(ya0.w), to_tf32(xa1.w), to_tf32(ya1.w));
        Bs2[kbB][nB][0]      = make_float2(to_tf32(u0.x), to_tf32(u1.x));
        Bs2[kbB][nB][1]      = make_float2(to_tf32(u0.y), to_tf32(u1.y));
        Bs2[kbB][nB][2]      = make_float2(to_tf32(u0.z), to_tf32(u1.z));
        Bs2[kbB][nB][3]      = make_float2(to_tf32(u0.w), to_tf32(u1.w));
        Bs2[kbB][nB + 64][0] = make_float2(to_tf32(v0.x), to_tf32(v1.x));
        Bs2[kbB][nB + 64][1] = make_float2(to_tf32(v0.y), to_tf32(v1.y));
        Bs2[kbB][nB + 64][2] = make_float2(to_tf32(v0.z), to_tf32(v1.z));
        Bs2[kbB][nB + 64][3] = make_float2(to_tf32(v0.w), to_tf32(v1.w));
        __syncthreads();

        int kn = k0 + 32;
        if (kn < K) {
            xa0 = *(const float4*)(a1p + kn);     xa1 = *(const float4*)(a1p + kn + 4);
            ya0 = *(const float4*)(a2p + kn);     ya1 = *(const float4*)(a2p + kn + 4);
            u0  = *(const float4*)(b1p + kn);     u1  = *(const float4*)(b1p + kn + 4);
            v0  = *(const float4*)(b2p + kn);     v1  = *(const float4*)(b2p + kn + 4);
        }

#pragma unroll
        for (int kb = 0; kb < 4; kb++) {
            float4 af[4]; float2 bf[4];
#pragma unroll
            for (int mt = 0; mt < 4; mt++)
                af[mt] = As4[kb][((warp_m * 4 + mt) << 3) + t4][c4];
#pragma unroll
            for (int nt = 0; nt < 4; nt++)
                bf[nt] = Bs2[kb][warp_n * 32 + nt * 8 + t4][c4];
#pragma unroll
            for (int mt = 0; mt < 4; mt++)
#pragma unroll
                for (int nt = 0; nt < 4; nt++) mma8(acc[mt][nt], af[mt], bf[nt]);
        }
    }

#pragma unroll
    for (int mt = 0; mt < 4; mt++) {
        int r0 = blockIdx.y * 128 + warp_m * 64 + mt * 16 + t4;
#pragma unroll
        for (int nt = 0; nt < 4; nt++) {
            int cc = blockIdx.x * 128 + warp_n * 32 + nt * 8 + 2 * c4;
            float b0 = bias[cc], b1 = bias[cc + 1];
            *(float2*)&C[(size_t)r0 * ldc + cc] =
                make_float2(acc[mt][nt][0] + b0, acc[mt][nt][1] + b1);
            *(float2*)&C[(size_t)(r0 + 8) * ldc + cc] =
                make_float2(acc[mt][nt][2] + b0, acc[mt][nt][3] + b1);
        }
    }
}

// ---------------------------------------------------------------------------
// RoPE (in place on q,k slices of g_qkv)
// ---------------------------------------------------------------------------
__global__ void rope_kernel(float* __restrict__ qkv)
{
    int idx = blockIdx.x * blockDim.x + threadIdx.x;
    const int total = S * NH * 16 * 2;
    if (idx >= total) return;

    int i = idx & 15;
    int r = idx >> 4;
    int h = r & 31;
    r >>= 5;
    int which = r & 1;
    int s = r >> 1;

    float inv = powf(10000.0f, -(float)i / 16.0f);
    float ang = (float)s * inv;
    float c, sn;
    sincosf(ang, &sn, &c);

    float* base = qkv + (size_t)s * QKV3 + h * HSTRIDE + which * HD;
    float x1 = base[i];
    float x2 = base[i + 16];
    base[i]      = x1 * c - x2 * sn;
    base[i + 16] = x2 * c + x1 * sn;
}

// ---------------------------------------------------------------------------
// Flash attention v4: 512 threads / 16 warps.
// Warp (wr, wh): QK  -> rows wr*16..+16  x keys wh*64..+64   (sc[8][4])
//                PV  -> rows wr*16..+16  x dims wh*64..+64   (o[8][4])
// Softmax: warp-local partials + 2-wide smem combine across halves.
// P stored tf32 in the Ks region (freed after QK) using flash2's proven
// A-frag write/read formulas. 4 __syncthreads per K-tile.
// Smem 194KB: Qs 64 | Ks/Pp 64 | Vs 64 | red_m 1K | red_s 1K.
// ---------------------------------------------------------------------------
__global__ __launch_bounds__(512, 1) void flash4(
    const float* __restrict__ qkv, float* __restrict__ ctx)
{
    extern __shared__ char smbase[];
    float4 (*Qs)[64][4]    = (float4 (*)[64][4])(smbase);              // [16][64][4]
    float2 (*Ks)[128][4]   = (float2 (*)[128][4])(smbase + 65536);     // [16][128][4]
    float4 (*Pp)[16][8][4] = (float4 (*)[16][8][4])(smbase + 65536);   // alias of Ks
    float2 (*Vs)[128][4]   = (float2 (*)[128][4])(smbase + 131072);    // [16][128][4]
    float  (*red_m)[2]     = (float (*)[2])(smbase + 196608);          // [128][2]
    float  (*red_s)[2]     = (float (*)[2])(smbase + 197632);          // [128][2]

    const int bi = (int)(gridDim.x - 1 - blockIdx.x);   // heavy tiles first
    const int h  = blockIdx.y;

    const int tid = threadIdx.x, lane = tid & 31, w = tid >> 5;
    const int wr = w >> 1, wh = w & 1;
    const int t4 = lane >> 2, c4 = lane & 3;

    // staging indices (512 threads)
    const int kbA = tid & 3, pA = (tid >> 2) & 63;
    const int m1  = ((pA >> 3) << 4) + (pA & 7);
    const int ccq = (tid >> 8) * 2;                 // covers cc = ccq, ccq+1
    const int dV  = tid & 127, kbV0 = (tid >> 7) & 3;

    const int c_base = (c4 & 1) * 2;
    const int c_hi   = (c4 >> 1) * 2;

    // ---- stage Q once (A-frag layout, tf32) ----
    {
        const float* a1p = qkv + (size_t)(bi * 128 + m1) * QKV3 + h * HSTRIDE;
        const float* a2p = a1p + (size_t)8 * QKV3;
#pragma unroll
        for (int u = 0; u < 2; u++) {
            int cc = ccq + u;
            const float* p1 = a1p + cc * 32 + kbA * 8;
            const float* p2 = a2p + cc * 32 + kbA * 8;
            float4 x0 = *(const float4*)p1, x1 = *(const float4*)(p1 + 4);
            float4 y0 = *(const float4*)p2, y1 = *(const float4*)(p2 + 4);
            int kb = cc * 4 + kbA;
            Qs[kb][pA][0] = make_float4(to_tf32(x0.x), to_tf32(y0.x), to_tf32(x1.x), to_tf32(y1.x));
            Qs[kb][pA][1] = make_float4(to_tf32(x0.y), to_tf32(y0.y), to_tf32(x1.y), to_tf32(y1.y));
            Qs[kb][pA][2] = make_float4(to_tf32(x0.z), to_tf32(y0.z), to_tf32(x1.z), to_tf32(y1.z));
            Qs[kb][pA][3] = make_float4(to_tf32(x0.w), to_tf32(y0.w), to_tf32(x1.w), to_tf32(y1.w));
        }
    }

    float o[8][4];
    float m_run[2] = { -1e30f, -1e30f };
    float l_run[2] = { 0.f, 0.f };
#pragma unroll
    for (int nt = 0; nt < 8; nt++)
#pragma unroll
        for (int r = 0; r < 4; r++) o[nt][r] = 0.f;

    const float scale = 0.08838834764831845f;   // 1/sqrt(128)
    const int r_lo = wr * 16 + t4;              // local row ids for stats
    const int r_hi = r_lo + 8;

    for (int bj = 0; bj <= bi; bj++) {
        // ---- stage K (B-frag into Ks) ----
        {
            const float* b1p = qkv + (size_t)(bj * 128 + pA) * QKV3 + h * HSTRIDE + HD;
            const float* b2p = b1p + (size_t)64 * QKV3;
#pragma unroll
            for (int u = 0; u < 2; u++) {
                int cc = ccq + u;
                const float* p1 = b1p + cc * 32 + kbA * 8;
                const float* p2 = b2p + cc * 32 + kbA * 8;
                float4 u0 = *(const float4*)p1, u1 = *(const float4*)(p1 + 4);
                float4 v0 = *(const float4*)p2, v1 = *(const float4*)(p2 + 4);
                int kb = cc * 4 + kbA;
                Ks[kb][pA][0]      = make_float2(to_tf32(u0.x), to_tf32(u1.x));
                Ks[kb][pA][1]      = make_float2(to_tf32(u0.y), to_tf32(u1.y));
                Ks[kb][pA][2]      = make_float2(to_tf32(u0.z), to_tf32(u1.z));
                Ks[kb][pA][3]      = make_float2(to_tf32(u0.w), to_tf32(u1.w));
                Ks[kb][pA + 64][0] = make_float2(to_tf32(v0.x), to_tf32(v1.x));
                Ks[kb][pA + 64][1] = make_float2(to_tf32(v0.y), to_tf32(v1.y));
                Ks[kb][pA + 64][2] = make_float2(to_tf32(v0.z), to_tf32(v1.z));
                Ks[kb][pA + 64][3] = make_float2(to_tf32(v0.w), to_tf32(v1.w));
            }
        }
        // ---- stage V (transposed: B[n=dim][k=key]) ----
        {
            const float* vcol = qkv + (size_t)(bj * 128) * QKV3 + h * HSTRIDE + 2 * HD + dV;
#pragma unroll
            for (int g = 0; g < 4; g++) {
                int kb = g * 4 + kbV0;
                float vv[8];
#pragma unroll
                for (int c = 0; c < 8; c++)
                    vv[c] = vcol[(size_t)(kb * 8 + c) * QKV3];
                Vs[kb][dV][0] = make_float2(to_tf32(vv[0]), to_tf32(vv[4]));
                Vs[kb][dV][1] = make_float2(to_tf32(vv[1]), to_tf32(vv[5]));
                Vs[kb][dV][2] = make_float2(to_tf32(vv[2]), to_tf32(vv[6]));
                Vs[kb][dV][3] = make_float2(to_tf32(vv[3]), to_tf32(vv[7]));
            }
        }
        __syncthreads();   // [S] staging visible (Q too, on first iter)

        // ---- Q @ K^T : warp (wr, wh) -> 16 rows x 64 keys ----
        float sc[8][4];
#pragma unroll
        for (int nt = 0; nt < 8; nt++)
#pragma unroll
            for (int r = 0; r < 4; r++) sc[nt][r] = 0.f;

#pragma unroll
        for (int kb = 0; kb < 16; kb++) {
            float4 af = Qs[kb][wr * 8 + t4][c4];
#pragma unroll
            for (int nt = 0; nt < 8; nt++) {
                float2 bf = Ks[kb][wh * 64 + nt * 8 + t4][c4];
                mma8(sc[nt], af, bf);
            }
        }

        // ---- scale + causal mask ----
        if (bj == bi) {
#pragma unroll
            for (int nt = 0; nt < 8; nt++) {
                int cc = wh * 64 + nt * 8 + 2 * c4;
                sc[nt][0] = (cc     <= r_lo) ? sc[nt][0] * scale : -1e30f;
                sc[nt][1] = (cc + 1 <= r_lo) ? sc[nt][1] * scale : -1e30f;
                sc[nt][2] = (cc     <= r_hi) ? sc[nt][2] * scale : -1e30f;
                sc[nt][3] = (cc + 1 <= r_hi) ? sc[nt][3] * scale : -1e30f;
            }
        } else {
#pragma unroll
            for (int nt = 0; nt < 8; nt++)
#pragma unroll
                for (int r = 0; r < 4; r++) sc[nt][r] *= scale;
        }

        // ---- half-row max (quad shfl) -> smem exchange ----
        float p0 = -1e30f, p1 = -1e30f;
#pragma unroll
        for (int nt = 0; nt < 8; nt++) {
            p0 = fmaxf(p0, fmaxf(sc[nt][0], sc[nt][1]));
            p1 = fmaxf(p1, fmaxf(sc[nt][2], sc[nt][3]));
        }
#pragma unroll
        for (int off = 1; off <= 2; off <<= 1) {
            p0 = fmaxf(p0, __shfl_xor_sync(0xffffffffu, p0, off));
            p1 = fmaxf(p1, __shfl_xor_sync(0xffffffffu, p1, off));
        }
        if (c4 == 0) {
            red_m[r_lo][wh] = p0;
            red_m[r_hi][wh] = p1;
        }
        __syncthreads();   // [A] QK reads of Ks done + max partials visible

        float M0 = fmaxf(red_m[r_lo][0], red_m[r_lo][1]);
        float M1 = fmaxf(red_m[r_hi][0], red_m[r_hi][1]);
        float mn0 = fmaxf(m_run[0], M0);
        float mn1 = fmaxf(m_run[1], M1);
        float a0 = __expf(m_run[0] - mn0);
        float a1 = __expf(m_run[1] - mn1);
        m_run[0] = mn0;  m_run[1] = mn1;

        // ---- exp + half-row sums ----
        float s0 = 0.f, s1 = 0.f;
#pragma unroll
        for (int nt = 0; nt < 8; nt++) {
            sc[nt][0] = __expf(sc[nt][0] - mn0);
            sc[nt][1] = __expf(sc[nt][1] - mn0);
            sc[nt][2] = __expf(sc[nt][2] - mn1);
            sc[nt][3] = __expf(sc[nt][3] - mn1);
            s0 += sc[nt][0] + sc[nt][1];
            s1 += sc[nt][2] + sc[nt][3];
        }
#pragma unroll
        for (int off = 1; off <= 2; off <<= 1) {
            s0 += __shfl_xor_sync(0xffffffffu, s0, off);
            s1 += __shfl_xor_sync(0xffffffffu, s1, off);
        }
        if (c4 == 0) {
            red_s[r_lo][wh] = s0;
            red_s[r_hi][wh] = s1;
        }

        // ---- write P (tf32) into Pp (= Ks region, free after [A]) ----
        // flash2's proven formulas; warp covers kb = wh*8 + nt.
#pragma unroll
        for (int nt = 0; nt < 8; nt++) {
            int kb = wh * 8 + nt;
            float* s0p = ((float*)&Pp[wr][kb][t4][c_base]) + c_hi;
            s0p[0] = to_tf32(sc[nt][0]);
            s0p[1] = to_tf32(sc[nt][2]);
            float* s1p = ((float*)&Pp[wr][kb][t4][c_base + 1]) + c_hi;
            s1p[0] = to_tf32(sc[nt][1]);
            s1p[1] = to_tf32(sc[nt][3]);
        }
        __syncthreads();   // [B] P + sum partials visible

        float ts0 = red_s[r_lo][0] + red_s[r_lo][1];
        float ts1 = red_s[r_hi][0] + red_s[r_hi][1];
        l_run[0] = l_run[0] * a0 + ts0;
        l_run[1] = l_run[1] * a1 + ts1;

        // rescale O
#pragma unroll
        for (int nt = 0; nt < 8; nt++) {
            o[nt][0] *= a0;  o[nt][1] *= a0;
            o[nt][2] *= a1;  o[nt][3] *= a1;
        }

        // ---- P @ V : warp (wr, wh) -> 16 rows x 64 dims ----
#pragma unroll
        for (int kb = 0; kb < 16; kb++) {
            float4 af = Pp[wr][kb][t4][c4];
#pragma unroll
            for (int nt = 0; nt < 8; nt++) {
                float2 bf = Vs[kb][wh * 64 + nt * 8 + t4][c4];
                mma8(o[nt], af, bf);
            }
        }
        __syncthreads();   // [C] Pp/Vs reads done before next staging
    }

    // ---- epilogue: normalize + store ----
    float inv0 = 1.0f / l_run[0];
    float inv1 = 1.0f / l_run[1];
    int row = bi * 128 + wr * 16 + t4;
#pragma unroll
    for (int nt = 0; nt < 8; nt++) {
        int col = h * HD + wh * 64 + nt * 8 + 2 * c4;
        *(float2*)&ctx[(size_t)row * Hdim + col] =
            make_float2(o[nt][0] * inv0, o[nt][1] * inv0);
        *(float2*)&ctx[(size_t)(row + 8) * Hdim + col] =
            make_float2(o[nt][2] * inv1, o[nt][3] * inv1);
    }
}

// ---------------------------------------------------------------------------
// Launch
// ---------------------------------------------------------------------------
extern "C" void kernel_launch(void* const* d_in, const int* in_sizes, int n_in,
                              void* d_out, int out_size)
{
    const float* hidden  = (const float*)d_in[0];
    // d_in[1] = attention_mask (causal; structure known, unused)
    const float* W_qkv   = (const float*)d_in[2];
    const float* b_qkv   = (const float*)d_in[3];
    const float* W_dense = (const float*)d_in[4];
    const float* b_dense = (const float*)d_in[5];
    float* out = (float*)d_out;

    float *qkv, *ctx;
    cudaGetSymbolAddress((void**)&qkv, g_qkv);
    cudaGetSymbolAddress((void**)&ctx, g_ctx);

    // 1) QKV GEMM: [2048,4096] x [12288,4096]^T -> [2048,12288]
    {
        dim3 grid(QKV3 / 128, S / 128);
        gemm_tc_nt<<<grid, 256>>>(hidden, W_qkv, b_qkv, qkv,
                                  Hdim, Hdim, Hdim, QKV3);
    }

    // 2) RoPE in place on q,k
    {
        int total = S * NH * 16 * 2;
        rope_kernel<<<(total + 255) / 256, 256>>>(qkv);
    }

    // 3-5) Fused flash attention v4 -> ctx [2048, 4096]
    {
        const int smem_bytes = 194 * 1024;
        cudaFuncSetAttribute(flash4, cudaFuncAttributeMaxDynamicSharedMemorySize,
                             smem_bytes);
        dim3 grid(S / 128, NH);
        flash4<<<grid, 512, smem_bytes>>>(qkv, ctx);
    }

    // 6) Dense GEMM: ctx [2048,4096] x W_dense^T -> out
    {
        dim3 grid(Hdim / 128, S / 128);
        gemm_tc_nt<<<grid, 256>>>(ctx, W_dense, b_dense, out,
                                  Hdim, Hdim, Hdim, Hdim);
    }
}